// round 9
// baseline (speedup 1.0000x reference)
#include <cuda_runtime.h>

#define HW   512
#define TX   64
#define TY   32
#define RSX  80   // TX + 16
#define RSY  48   // TY + 16
#define MSX  72   // TX + 8
#define MSY  40   // TY + 8
#define NT   512

// dynamic smem layout (floats)
#define OFF_SRAW 0
#define OFF_SHS  (RSY * RSX)                 // 3840
#define OFF_SRES (OFF_SHS + RSY * MSX)       // 7296
#define OFF_SHS2 (OFF_SRES + MSY * MSX)      // 10176
#define SMEM_FLOATS (OFF_SHS2 + MSY * TX)    // 12736
#define SMEM_BYTES (SMEM_FLOATS * 4)         // 50944

__device__ __forceinline__ int refl(int i) {
    i = ::abs(i);
    return i < HW ? i : (2 * HW - 2 - i);
}

// asinh(x) = sign(x) * log(|x| + sqrt(x^2+1)); sqrt via v*rsqrt(v) (v>=1)
__device__ __forceinline__ float fast_asinh(float x) {
    float ax = fabsf(x);
    float v  = fmaf(ax, ax, 1.0f);
    float s  = v * rsqrtf(v);
    float r  = __logf(ax + s);
    return copysignf(r, x);
}

__global__ __launch_bounds__(NT) void imgnorm_kernel(
    const float* __restrict__ img, const float* __restrict__ bg,
    const float* __restrict__ thr, const float* __restrict__ scl,
    float* __restrict__ out)
{
    extern __shared__ float smem[];
    float* sraw = smem + OFF_SRAW;   // [48][80]
    float* shs  = smem + OFF_SHS;    // [48][72]  (aliased as sbox [32][64] after ph3)
    float* sres = smem + OFF_SRES;   // [40][72]
    float* shs2 = smem + OFF_SHS2;   // [40][64]
#define SRAW(r, c) sraw[(r) * RSX + (c)]
#define SHS(r, c)  shs [(r) * MSX + (c)]
#define SBOX(r, c) shs [(r) * TX  + (c)]
#define SRES(r, c) sres[(r) * MSX + (c)]
#define SHS2(r, c) shs2[(r) * TX  + (c)]
#define LD2(p)  (*(const float2*)&(p))
#define ST2(p)  (*(float2*)&(p))

    const int bc  = blockIdx.z;            // b*5 + c
    const int tx0 = blockIdx.x * TX;
    const int ty0 = blockIdx.y * TY;
    const float* im  = img + (size_t)bc * HW * HW;
    const float* bgp = bg  + (size_t)bc * HW * HW;
    const int tid = threadIdx.x;
    const float inv81 = 1.0f / 81.0f;

    // Phase 1: load 48x80 raw tile. Interior blocks: vectorized LDG.128.
    const bool interior = (tx0 >= 8) && (tx0 + RSX - 8 <= HW) &&
                          (ty0 >= 8) && (ty0 + RSY - 8 <= HW);
    if (interior) {
        const float* base = im + (ty0 - 8) * HW + (tx0 - 8);
        for (int t = tid; t < RSY * (RSX / 4); t += NT) {       // 960 tasks
            int r = t / 20, c4 = (t - r * 20) * 4;
            *(float4*)&SRAW(r, c4) = *(const float4*)&base[r * HW + c4];
        }
    } else {
        for (int i = tid; i < RSY * RSX; i += NT) {             // 3840 tasks
            int r = i / RSX, c = i - r * RSX;
            SRAW(r, c) = im[refl(ty0 + r - 8) * HW + refl(tx0 + c - 8)];
        }
    }
    __syncthreads();

    // Phase 2: horizontal 9-sums of raw, 48 rows x 72 cols (4 outs/task, contiguous)
    for (int t = tid; t < RSY * (MSX / 4); t += NT) {           // 864 tasks
        int r = t / 18, c4 = (t - r * 18) * 4;
        float4 a = *(const float4*)&SRAW(r, c4);
        float4 b = *(const float4*)&SRAW(r, c4 + 4);
        float4 c = *(const float4*)&SRAW(r, c4 + 8);
        float s0 = ((a.x + a.y) + (a.z + a.w)) + ((b.x + b.y) + (b.z + b.w)) + c.x;
        float s1 = s0 - a.x + c.y;
        float s2 = s1 - a.y + c.z;
        float s3 = s2 - a.z + c.w;
        *(float4*)&SHS(r, c4) = make_float4(s0, s1, s2, s3);
    }
    __syncthreads();

    // Phase 3: vertical 9-sums -> mean -> res, 40x72.
    // float2 column-pairs, 4-row register sliding window (same bytes as scalar,
    // half the smem instructions).
    for (int t = tid; t < (MSY / 4) * (MSX / 2); t += NT) {     // 360 tasks
        int rg = t / 36, cp = t - rg * 36;
        int c = cp * 2, r0 = rg * 4;
        float2 a0 = LD2(SHS(r0, c)), a1 = LD2(SHS(r0 + 1, c)), a2 = LD2(SHS(r0 + 2, c));
        float2 s = make_float2(a0.x + a1.x + a2.x, a0.y + a1.y + a2.y);
        #pragma unroll
        for (int k = 3; k < 9; k++) {
            float2 w = LD2(SHS(r0 + k, c));
            s.x += w.x; s.y += w.y;
        }
        float2 rv = LD2(SRAW(r0 + 4, c + 4));
        ST2(SRES(r0 + 0, c)) = make_float2(rv.x - s.x * inv81, rv.y - s.y * inv81);
        float2 w9 = LD2(SHS(r0 + 9, c));
        s.x += w9.x - a0.x; s.y += w9.y - a0.y;
        rv = LD2(SRAW(r0 + 5, c + 4));
        ST2(SRES(r0 + 1, c)) = make_float2(rv.x - s.x * inv81, rv.y - s.y * inv81);
        float2 wA = LD2(SHS(r0 + 10, c));
        s.x += wA.x - a1.x; s.y += wA.y - a1.y;
        rv = LD2(SRAW(r0 + 6, c + 4));
        ST2(SRES(r0 + 2, c)) = make_float2(rv.x - s.x * inv81, rv.y - s.y * inv81);
        float2 wB = LD2(SHS(r0 + 11, c));
        s.x += wB.x - a2.x; s.y += wB.y - a2.y;
        rv = LD2(SRAW(r0 + 7, c + 4));
        ST2(SRES(r0 + 3, c)) = make_float2(rv.x - s.x * inv81, rv.y - s.y * inv81);
    }
    __syncthreads();

    // Phase 4: horizontal 9-sums of res^2, 40 rows x 64 cols (4 outs/task, contiguous)
    for (int t = tid; t < MSY * (TX / 4); t += NT) {            // 640 tasks
        int r = t >> 4, c4 = (t & 15) * 4;
        float4 a = *(const float4*)&SRES(r, c4);
        float4 b = *(const float4*)&SRES(r, c4 + 4);
        float4 c = *(const float4*)&SRES(r, c4 + 8);
        float q0 = a.x*a.x, q1 = a.y*a.y, q2 = a.z*a.z, q3 = a.w*a.w;
        float q4 = b.x*b.x, q5 = b.y*b.y, q6 = b.z*b.z, q7 = b.w*b.w;
        float q8 = c.x*c.x, q9 = c.y*c.y, q10 = c.z*c.z, q11 = c.w*c.w;
        float s0 = ((q0 + q1) + (q2 + q3)) + ((q4 + q5) + (q6 + q7)) + q8;
        float s1 = s0 - q0 + q9;
        float s2 = s1 - q1 + q10;
        float s3 = s2 - q2 + q11;
        *(float4*)&SHS2(r, c4) = make_float4(s0, s1, s2, s3);
    }
    __syncthreads();

    // Phase 4.5: vertical 9-sum of shs2 -> SBOX (aliased over shs), 32x64.
    // float2 column-pairs, 2-row groups: exactly 1 task/thread, perfect balance.
    {
        int cp = tid & 31;                 // column pair 0..31
        int r0 = (tid >> 5) * 2;           // row group 0..15 -> rows r0, r0+1
        int c  = cp * 2;
        float2 a0 = LD2(SHS2(r0, c));
        float2 s = a0;
        #pragma unroll
        for (int k = 1; k < 9; k++) {
            float2 w = LD2(SHS2(r0 + k, c));
            s.x += w.x; s.y += w.y;
        }
        ST2(SBOX(r0 + 0, c)) = s;
        float2 w9 = LD2(SHS2(r0 + 9, c));
        s.x += w9.x - a0.x; s.y += w9.y - a0.y;
        ST2(SBOX(r0 + 1, c)) = s;
    }
    __syncthreads();

    // Per-channel asinh constants (broadcast loads)
    const int cb = bc % 5;
    const float th0 = thr[cb * 3 + 0], th1 = thr[cb * 3 + 1], th2 = thr[cb * 3 + 2];
    const float sc0 = __expf(scl[cb * 3 + 0]);
    const float sc1 = __expf(scl[cb * 3 + 1]);
    const float sc2 = __expf(scl[cb * 3 + 2]);

    // Phase 5: row-wise, 4 adjacent pixels per thread — everything float4.
    const int row = tid >> 4;          // 0..31
    const int c4  = (tid & 15) << 2;   // 0..60
    const int gy  = ty0 + row;
    const int gx0 = tx0 + c4;
    const size_t CH = (size_t)HW * HW;
    const size_t p  = (size_t)bc * 7 * CH + (size_t)gy * HW + gx0;

    float raw[4], res[4], bgv[4], vv[4];
    *(float4*)raw = *(const float4*)&SRAW(row + 8, c4 + 8);
    *(float4*)res = *(const float4*)&SRES(row + 4, c4 + 4);
    *(float4*)vv  = *(const float4*)&SBOX(row, c4);
    *(float4*)bgv = *(const float4*)&bgp[(size_t)gy * HW + gx0];

    float l0[4], l1[4], cl[4], a0[4], a1[4], a2[4];
    #pragma unroll
    for (int j = 0; j < 4; j++) {
        float m = vv[j] * inv81;
        cl[j] = res[j] * rsqrtf(fmaxf(m, 1.0f));
        float off = (raw[j] - bgv[j]) * rsqrtf(bgv[j]);
        l0[j] = __logf(fmaxf(off + 1.0f, 1.0f));
        l1[j] = __logf(fmaxf(off,        1.0f));
        a0[j] = fast_asinh((raw[j] - th0) * sc0);
        a1[j] = fast_asinh((raw[j] - th1) * sc1);
        a2[j] = fast_asinh((raw[j] - th2) * sc2);
    }

    *(float4*)&out[p]          = *(float4*)raw;
    *(float4*)&out[p + 1 * CH] = *(float4*)l0;
    *(float4*)&out[p + 2 * CH] = *(float4*)l1;
    *(float4*)&out[p + 3 * CH] = *(float4*)cl;
    *(float4*)&out[p + 4 * CH] = *(float4*)a0;
    *(float4*)&out[p + 5 * CH] = *(float4*)a1;
    *(float4*)&out[p + 6 * CH] = *(float4*)a2;
}

extern "C" void kernel_launch(void* const* d_in, const int* in_sizes, int n_in,
                              void* d_out, int out_size) {
    const float* img = (const float*)d_in[0];
    const float* bg  = (const float*)d_in[1];
    const float* thr = (const float*)d_in[2];
    const float* scl = (const float*)d_in[3];
    float* out = (float*)d_out;
    cudaFuncSetAttribute(imgnorm_kernel,
                         cudaFuncAttributeMaxDynamicSharedMemorySize, SMEM_BYTES);
    dim3 grid(HW / TX, HW / TY, 8 * 5);
    imgnorm_kernel<<<grid, NT, SMEM_BYTES>>>(img, bg, thr, scl, out);
}

// round 10
// speedup vs baseline: 1.0661x; 1.0661x over previous
#include <cuda_runtime.h>

#define HW   512
#define TX   64
#define TY   32
#define RSX  80   // TX + 16
#define RSY  48   // TY + 16
#define MSX  72   // TX + 8
#define MSY  40   // TY + 8
#define NT   512

// dynamic smem layout (floats)
#define OFF_SRAW 0
#define OFF_SHS  (RSY * RSX)                 // 3840
#define OFF_SRES (OFF_SHS + RSY * MSX)       // 7296
#define OFF_SHS2 (OFF_SRES + MSY * MSX)      // 10176
#define SMEM_FLOATS (OFF_SHS2 + MSY * TX)    // 12736
#define SMEM_BYTES (SMEM_FLOATS * 4)         // 50944

__device__ __forceinline__ int refl(int i) {
    i = ::abs(i);
    return i < HW ? i : (2 * HW - 2 - i);
}

// asinh(x) = sign(x) * log(|x| + sqrt(x^2+1)); sqrt via v*rsqrt(v) (v>=1)
__device__ __forceinline__ float fast_asinh(float x) {
    float ax = fabsf(x);
    float v  = fmaf(ax, ax, 1.0f);
    float s  = v * rsqrtf(v);
    float r  = __logf(ax + s);
    return copysignf(r, x);
}

__global__ __launch_bounds__(NT, 4) void imgnorm_kernel(
    const float* __restrict__ img, const float* __restrict__ bg,
    const float* __restrict__ thr, const float* __restrict__ scl,
    float* __restrict__ out)
{
    extern __shared__ float smem[];
    float* sraw = smem + OFF_SRAW;   // [48][80]
    float* shs  = smem + OFF_SHS;    // [48][72]  (aliased as sbox [32][64] after ph3)
    float* sres = smem + OFF_SRES;   // [40][72]
    float* shs2 = smem + OFF_SHS2;   // [40][64]
#define SRAW(r, c) sraw[(r) * RSX + (c)]
#define SHS(r, c)  shs [(r) * MSX + (c)]
#define SBOX(r, c) shs [(r) * TX  + (c)]
#define SRES(r, c) sres[(r) * MSX + (c)]
#define SHS2(r, c) shs2[(r) * TX  + (c)]
#define LD2(p)  (*(const float2*)&(p))
#define ST2(p)  (*(float2*)&(p))

    const int bc  = blockIdx.z;            // b*5 + c
    const int tx0 = blockIdx.x * TX;
    const int ty0 = blockIdx.y * TY;
    const float* im  = img + (size_t)bc * HW * HW;
    const float* bgp = bg  + (size_t)bc * HW * HW;
    const int tid = threadIdx.x;
    const float inv81 = 1.0f / 81.0f;

    // Phase 1: load 48x80 raw tile. Interior blocks: vectorized LDG.128.
    const bool interior = (tx0 >= 8) && (tx0 + RSX - 8 <= HW) &&
                          (ty0 >= 8) && (ty0 + RSY - 8 <= HW);
    if (interior) {
        const float* base = im + (ty0 - 8) * HW + (tx0 - 8);
        for (int t = tid; t < RSY * (RSX / 4); t += NT) {       // 960 tasks
            int r = t / 20, c4 = (t - r * 20) * 4;
            *(float4*)&SRAW(r, c4) = *(const float4*)&base[r * HW + c4];
        }
    } else {
        for (int i = tid; i < RSY * RSX; i += NT) {             // 3840 tasks
            int r = i / RSX, c = i - r * RSX;
            SRAW(r, c) = im[refl(ty0 + r - 8) * HW + refl(tx0 + c - 8)];
        }
    }
    __syncthreads();

    // Phase 2: horizontal 9-sums of raw, 48 rows x 72 cols (4 outs/task, contiguous)
    for (int t = tid; t < RSY * (MSX / 4); t += NT) {           // 864 tasks
        int r = t / 18, c4 = (t - r * 18) * 4;
        float4 a = *(const float4*)&SRAW(r, c4);
        float4 b = *(const float4*)&SRAW(r, c4 + 4);
        float4 c = *(const float4*)&SRAW(r, c4 + 8);
        float s0 = ((a.x + a.y) + (a.z + a.w)) + ((b.x + b.y) + (b.z + b.w)) + c.x;
        float s1 = s0 - a.x + c.y;
        float s2 = s1 - a.y + c.z;
        float s3 = s2 - a.z + c.w;
        *(float4*)&SHS(r, c4) = make_float4(s0, s1, s2, s3);
    }
    __syncthreads();

    // Phase 3: vertical 9-sums -> mean -> res, 40x72.
    // float2 column-pairs, 4-row register sliding window (same bytes as scalar,
    // half the smem instructions). Register-lean: only a0,a1 retained; a2
    // re-loaded at its subtraction point.
    for (int t = tid; t < (MSY / 4) * (MSX / 2); t += NT) {     // 360 tasks
        int rg = t / 36, cp = t - rg * 36;
        int c = cp * 2, r0 = rg * 4;
        float2 a0 = LD2(SHS(r0, c)), a1 = LD2(SHS(r0 + 1, c));
        float2 s = make_float2(a0.x + a1.x, a0.y + a1.y);
        #pragma unroll
        for (int k = 2; k < 9; k++) {
            float2 w = LD2(SHS(r0 + k, c));
            s.x += w.x; s.y += w.y;
        }
        float2 rv = LD2(SRAW(r0 + 4, c + 4));
        ST2(SRES(r0 + 0, c)) = make_float2(rv.x - s.x * inv81, rv.y - s.y * inv81);
        float2 w9 = LD2(SHS(r0 + 9, c));
        s.x += w9.x - a0.x; s.y += w9.y - a0.y;
        rv = LD2(SRAW(r0 + 5, c + 4));
        ST2(SRES(r0 + 1, c)) = make_float2(rv.x - s.x * inv81, rv.y - s.y * inv81);
        float2 wA = LD2(SHS(r0 + 10, c));
        s.x += wA.x - a1.x; s.y += wA.y - a1.y;
        rv = LD2(SRAW(r0 + 6, c + 4));
        ST2(SRES(r0 + 2, c)) = make_float2(rv.x - s.x * inv81, rv.y - s.y * inv81);
        float2 wB = LD2(SHS(r0 + 11, c));
        float2 a2 = LD2(SHS(r0 + 2, c));
        s.x += wB.x - a2.x; s.y += wB.y - a2.y;
        rv = LD2(SRAW(r0 + 7, c + 4));
        ST2(SRES(r0 + 3, c)) = make_float2(rv.x - s.x * inv81, rv.y - s.y * inv81);
    }
    __syncthreads();

    // Phase 4: horizontal 9-sums of res^2, 40 rows x 64 cols (4 outs/task, contiguous)
    for (int t = tid; t < MSY * (TX / 4); t += NT) {            // 640 tasks
        int r = t >> 4, c4 = (t & 15) * 4;
        float4 a = *(const float4*)&SRES(r, c4);
        float4 b = *(const float4*)&SRES(r, c4 + 4);
        float4 c = *(const float4*)&SRES(r, c4 + 8);
        float q0 = a.x*a.x, q1 = a.y*a.y, q2 = a.z*a.z, q3 = a.w*a.w;
        float q4 = b.x*b.x, q5 = b.y*b.y, q6 = b.z*b.z, q7 = b.w*b.w;
        float q8 = c.x*c.x, q9 = c.y*c.y, q10 = c.z*c.z, q11 = c.w*c.w;
        float s0 = ((q0 + q1) + (q2 + q3)) + ((q4 + q5) + (q6 + q7)) + q8;
        float s1 = s0 - q0 + q9;
        float s2 = s1 - q1 + q10;
        float s3 = s2 - q2 + q11;
        *(float4*)&SHS2(r, c4) = make_float4(s0, s1, s2, s3);
    }
    __syncthreads();

    // Phase 4.5: vertical 9-sum of shs2 -> SBOX (aliased over shs), 32x64.
    // float2 column-pairs, 2-row groups: exactly 1 task/thread, perfect balance.
    {
        int cp = tid & 31;                 // column pair 0..31
        int r0 = (tid >> 5) * 2;           // row group 0..15 -> rows r0, r0+1
        int c  = cp * 2;
        float2 a0 = LD2(SHS2(r0, c));
        float2 s = a0;
        #pragma unroll
        for (int k = 1; k < 9; k++) {
            float2 w = LD2(SHS2(r0 + k, c));
            s.x += w.x; s.y += w.y;
        }
        ST2(SBOX(r0 + 0, c)) = s;
        float2 w9 = LD2(SHS2(r0 + 9, c));
        s.x += w9.x - a0.x; s.y += w9.y - a0.y;
        ST2(SBOX(r0 + 1, c)) = s;
    }
    __syncthreads();

    // Per-channel asinh constants (broadcast loads)
    const int cb = bc % 5;
    const float th0 = thr[cb * 3 + 0], th1 = thr[cb * 3 + 1], th2 = thr[cb * 3 + 2];
    const float sc0 = __expf(scl[cb * 3 + 0]);
    const float sc1 = __expf(scl[cb * 3 + 1]);
    const float sc2 = __expf(scl[cb * 3 + 2]);

    // Phase 5: row-wise, 4 adjacent pixels per thread — everything float4.
    const int row = tid >> 4;          // 0..31
    const int c4  = (tid & 15) << 2;   // 0..60
    const int gy  = ty0 + row;
    const int gx0 = tx0 + c4;
    const size_t CH = (size_t)HW * HW;
    const size_t p  = (size_t)bc * 7 * CH + (size_t)gy * HW + gx0;

    float raw[4], res[4], bgv[4], vv[4];
    *(float4*)raw = *(const float4*)&SRAW(row + 8, c4 + 8);
    *(float4*)res = *(const float4*)&SRES(row + 4, c4 + 4);
    *(float4*)vv  = *(const float4*)&SBOX(row, c4);
    *(float4*)bgv = *(const float4*)&bgp[(size_t)gy * HW + gx0];

    float l0[4], l1[4], cl[4], a0[4], a1[4], a2[4];
    #pragma unroll
    for (int j = 0; j < 4; j++) {
        float m = vv[j] * inv81;
        cl[j] = res[j] * rsqrtf(fmaxf(m, 1.0f));
        float off = (raw[j] - bgv[j]) * rsqrtf(bgv[j]);
        l0[j] = __logf(fmaxf(off + 1.0f, 1.0f));
        l1[j] = __logf(fmaxf(off,        1.0f));
        a0[j] = fast_asinh((raw[j] - th0) * sc0);
        a1[j] = fast_asinh((raw[j] - th1) * sc1);
        a2[j] = fast_asinh((raw[j] - th2) * sc2);
    }

    *(float4*)&out[p]          = *(float4*)raw;
    *(float4*)&out[p + 1 * CH] = *(float4*)l0;
    *(float4*)&out[p + 2 * CH] = *(float4*)l1;
    *(float4*)&out[p + 3 * CH] = *(float4*)cl;
    *(float4*)&out[p + 4 * CH] = *(float4*)a0;
    *(float4*)&out[p + 5 * CH] = *(float4*)a1;
    *(float4*)&out[p + 6 * CH] = *(float4*)a2;
}

extern "C" void kernel_launch(void* const* d_in, const int* in_sizes, int n_in,
                              void* d_out, int out_size) {
    const float* img = (const float*)d_in[0];
    const float* bg  = (const float*)d_in[1];
    const float* thr = (const float*)d_in[2];
    const float* scl = (const float*)d_in[3];
    float* out = (float*)d_out;
    cudaFuncSetAttribute(imgnorm_kernel,
                         cudaFuncAttributeMaxDynamicSharedMemorySize, SMEM_BYTES);
    dim3 grid(HW / TX, HW / TY, 8 * 5);
    imgnorm_kernel<<<grid, NT, SMEM_BYTES>>>(img, bg, thr, scl, out);
}